// round 15
// baseline (speedup 1.0000x reference)
#include <cuda_runtime.h>
#include <cuda_fp16.h>
#include <cstdint>

// Problem constants
#define B_  128
#define C2_ 14
#define S_  14
#define H_  256

#define THREADS 224   // 7 warps

// A (x window) smem geometry, word units (1 word = 4B = 1 half2 slot):
//   addr = 336*plane + 24*n + slot ;  336 = 14*24 so 336*mr+24*nr = 24*r
//   row stride 24 (== 24 mod 32) -> LDS.64 banks 24q+2t conflict-free
#define ROW_S   24
#define PLANE_S 336
#define XBUF_W  (9 * PLANE_S)        // 3024 words per buffer (9 planes)
#define BS_W    (2 * XBUF_W)         // 6048
#define BS_BUF  (64 * ROW_S)         // 1536 words per B chunk (N=64)
#define NBUF_B  4
#define CS_STRIDE 68
#define SMEM_WORDS (BS_W + NBUF_B * BS_BUF)   // 12192 words = 48768 B

// Packed fp16 k-pair scratch (rebuilt each launch)
#define WPRE_N (12 * 4 * 64 * 16)               // 49152 half2
__device__ __half2 g_xpre[(size_t)B_ * 16 * 14 * 64];   // 7.3 MB
__device__ __half2 g_wpre[WPRE_N];                      // 196 KB

// number of 448-thread blocks for the w part of prep
#define WBLK ((WPRE_N + 447) / 448)             // 110

// slot s -> pair p  (inverse of addr(p) = (p&8)|((p&3)<<1)|((p&4)>>2))
__device__ __forceinline__ int slot2pair(int s) {
    return (s & 8) | ((s >> 1) & 3) | ((s & 1) << 2);
}

__device__ __forceinline__ void mma_f16(float c[4],
                                        unsigned a0, unsigned a1, unsigned a2, unsigned a3,
                                        unsigned b0, unsigned b1) {
    asm volatile(
        "mma.sync.aligned.m16n8k16.row.col.f32.f16.f16.f32 "
        "{%0,%1,%2,%3}, {%4,%5,%6,%7}, {%8,%9}, {%0,%1,%2,%3};"
        : "+f"(c[0]), "+f"(c[1]), "+f"(c[2]), "+f"(c[3])
        : "r"(a0), "r"(a1), "r"(a2), "r"(a3), "r"(b0), "r"(b1));
}

__device__ __forceinline__ void cp16(unsigned dst, const void* src) {
    asm volatile("cp.async.cg.shared.global [%0], [%1], 16;"
                 :: "r"(dst), "l"(src) : "memory");
}
#define CP_COMMIT() asm volatile("cp.async.commit_group;" ::: "memory")
#define CP_WAIT2()  asm volatile("cp.async.wait_group 2;" ::: "memory")

// ---------------------------------------------------------------------------
// prep (merged): blocks [0,1024) build xpre (one (jb,b) slice each, 8 of 16
// planes selected by ph = bx>>9); blocks [1024, 1024+WBLK) build wpre.
//   xpre[b][mp:16][n:14][jb:4][slot:16] : half2 = (j=2p, j=2p+1), planes 0,15 = 0
//   wpre[c:12][hq:4][n:64][slot:16]     : half2 w1 k-pairs for chunk c
// ---------------------------------------------------------------------------
__global__ __launch_bounds__(448) void prep_kernel(
    const float* __restrict__ x, const float* __restrict__ w1)
{
    const int bx  = blockIdx.x;
    const int tid = threadIdx.x;

    if (bx < 1024) {
        // ---- x part ----
        __shared__ float xs[6272];
        const int jb = bx & 3;
        const int b  = (bx >> 2) & 127;
        const int ph = bx >> 9;            // 0,1: which 8 planes

        const float4* src = reinterpret_cast<const float4*>(
            x + (size_t)b * 25088 + jb * 6272);
#pragma unroll
        for (int k = 0; k < 4; ++k) {
            int p = tid + k * 448;
            if (p < 1568) reinterpret_cast<float4*>(xs)[p] = __ldg(src + p);
        }
        __syncthreads();

        const int half = tid >= 224;
        const int sub  = tid - 224 * half;
        const int nn   = sub >> 4;
        const int s    = sub & 15;
        const int pp   = slot2pair(s);
        const float* r0 = xs + (2 * pp)     * 196 + nn * 14;
        const float* r1 = xs + (2 * pp + 1) * 196 + nn * 14;

        __half2* wb = g_xpre + ((size_t)b * 16 * 14 + nn) * 64 + jb * 16 + s;
#pragma unroll
        for (int k = 0; k < 4; ++k) {
            int mp = ph * 8 + half * 4 + k;
            __half2 v = (mp >= 1 && mp <= 14)
                      ? __floats2half2_rn(r0[mp - 1], r1[mp - 1])
                      : __floats2half2_rn(0.0f, 0.0f);
            wb[(size_t)mp * 14 * 64] = v;
        }
    } else {
        // ---- w part: WPRE_N half2 over WBLK blocks x 448 threads ----
        int idx = (bx - 1024) * 448 + tid;
        if (idx < WPRE_N) {
            int s  = idx & 15;
            int n  = (idx >> 4) & 63;
            int hq = (idx >> 10) & 3;
            int c  = idx >> 12;
            int jb = c / 3;
            int ii = c - 3 * jb;
            int pp = slot2pair(s);
            int j  = jb * 32 + 2 * pp;
            int h  = hq * 64 + n;
            float lo = __ldg(w1 + (size_t)(j * 3 + ii) * H_ + h);
            float hi = __ldg(w1 + (size_t)((j + 1) * 3 + ii) * H_ + h);
            g_wpre[idx] = __floats2half2_rn(lo, hi);
        }
    }
}

// ---------------------------------------------------------------------------
// Fused fp16 GEMM + roll epilogue. Block = (b, m-half, 64-h chunk).
// M=112 rows r=(m_loc*14+n), N=64, K=384 in 12 chunks of 32 (2 k16 MMAs each).
// cp.async: B 4-deep, x 2-deep, distance 3, wait_group 2.
// ---------------------------------------------------------------------------
__global__ void __launch_bounds__(THREADS, 3) fused_kernel(
    const float* __restrict__ w0,      // (H, 2)
    const int*   __restrict__ shift_p, // scalar (may be null -> 1)
    float*       __restrict__ out)     // (B, H, C2, S)
{
    extern __shared__ float sm[];
    unsigned sbase;
    asm("{ .reg .u64 t; cvta.to.shared.u64 t, %1; cvt.u32.u64 %0, t; }"
        : "=r"(sbase) : "l"(sm));

    const int bid = blockIdx.x;
    const int b   = bid >> 3;
    const int mh  = (bid >> 2) & 1;
    const int hh  = bid & 3;
    const int h0  = hh * 64;

    const int tid  = threadIdx.x;
    const int w    = tid >> 5;
    const int lane = tid & 31;
    const int t    = lane & 3;
    const int q    = lane >> 2;

    // ---- x staging indices: 126 rows x 4 segs = 504 cp16, 3/thread ----
    int xlp[3], xnn[3], xsg[3];
#pragma unroll
    for (int k = 0; k < 3; ++k) {
        int p = tid + k * THREADS;
        if (p < 504) {
            int row = p >> 2;
            xsg[k] = p & 3;
            xlp[k] = row / 14;
            xnn[k] = row - xlp[k] * 14;
        } else xlp[k] = -1;
    }
    const __half2* xpb = g_xpre + ((size_t)b * 16 + 7 * mh) * 14 * 64;

    auto issue_x = [&](int jb) {
        unsigned dbase = sbase + (unsigned)((jb & 1) * XBUF_W) * 4u;
#pragma unroll
        for (int k = 0; k < 3; ++k) {
            if (xlp[k] >= 0) {
                const __half2* src = xpb + (size_t)(xlp[k] * 14 + xnn[k]) * 64
                                   + jb * 16 + xsg[k] * 4;
                unsigned dst = dbase + (unsigned)(PLANE_S * xlp[k] + ROW_S * xnn[k]
                                                  + 4 * xsg[k]) * 4u;
                cp16(dst, src);
            }
        }
    };
    // ---- B staging: 64 rows x 4 segs = 256 cp16, 2/thread ----
    auto issue_b = [&](int c2, int buf) {
        const __half2* bsrc = g_wpre + (size_t)(c2 * 4 + hh) * 1024;
        unsigned dbase = sbase + (unsigned)(BS_W + buf * BS_BUF) * 4u;
#pragma unroll
        for (int k = 0; k < 2; ++k) {
            int p = tid + k * THREADS;
            if (p < 256) {
                int row = p >> 2, seg = p & 3;
                cp16(dbase + (unsigned)(row * ROW_S + 4 * seg) * 4u,
                     bsrc + row * 16 + seg * 4);
            }
        }
    };

    // Per-thread A base offsets (words): rows q, q+8 of warp tile m16
    int pa[2];
#pragma unroll
    for (int u = 0; u < 2; ++u) {
        int r  = 16 * w + q + 8 * u;
        int mr = r / 14;
        int nr = r - mr * 14;
        if (mr > 6) mr = 6;            // pad rows -> harmless valid data
        pa[u] = PLANE_S * mr + ROW_S * nr + 2 * t;
    }

    // Prologue: x0 + B chunks 0,1,2
    issue_x(0);
    issue_b(0, 0);
    CP_COMMIT();
    issue_b(1, 1);
    CP_COMMIT();
    issue_b(2, 2);
    CP_COMMIT();

    float cf[8][4];
#pragma unroll
    for (int f = 0; f < 8; ++f)
#pragma unroll
        for (int r = 0; r < 4; ++r) cf[f][r] = 0.0f;

    const int pbq = ROW_S * q + 2 * t;

    // ---- Main loop: 12 chunks = 4 j-blocks x 3 i; 2 k16 MMA steps each ----
#pragma unroll 1
    for (int jb = 0; jb < 4; ++jb) {
        const int xw = (jb & 1) * XBUF_W;

#pragma unroll
        for (int ii = 0; ii < 3; ++ii) {
            CP_WAIT2();
            __syncthreads();

            const int c = 3 * jb + ii;
            if (ii == 0 && jb < 3) issue_x(jb + 1);
            if (c < 9) issue_b(c + 3, (c + 3) & 3);
            CP_COMMIT();

            const int bw = BS_W + (c & 3) * BS_BUF + pbq;
            const int aw = xw + PLANE_S * ii;

#pragma unroll
            for (int s = 0; s < 2; ++s) {
                const int ao = aw + 8 * s;
                float2 L1 = *reinterpret_cast<const float2*>(&sm[pa[0] + ao]);
                float2 L2 = *reinterpret_cast<const float2*>(&sm[pa[1] + ao]);
                unsigned a0 = __float_as_uint(L1.x), a2 = __float_as_uint(L1.y);
                unsigned a1 = __float_as_uint(L2.x), a3 = __float_as_uint(L2.y);
#pragma unroll
                for (int fn = 0; fn < 8; ++fn) {
                    float2 bp = *reinterpret_cast<const float2*>(
                        &sm[bw + fn * (8 * ROW_S) + 8 * s]);
                    mma_f16(cf[fn], a0, a1, a2, a3,
                            __float_as_uint(bp.x), __float_as_uint(bp.y));
                }
            }
        }
    }

    __syncthreads();   // C tile aliases x/B regions -> drain reads first

    // ---- Write C tile to smem rows [r][CS_STRIDE] (112 x 68 = 7616 w) ----
#pragma unroll
    for (int fn = 0; fn < 8; ++fn) {
        const float* cc = cf[fn];
        int r1  = 16 * w + q;
        int r2  = r1 + 8;
        int col = 8 * fn + 2 * t;
        *reinterpret_cast<float2*>(&sm[r1 * CS_STRIDE + col]) = make_float2(cc[0], cc[1]);
        *reinterpret_cast<float2*>(&sm[r2 * CS_STRIDE + col]) = make_float2(cc[2], cc[3]);
    }
    __syncthreads();

    // ---- Fused roll epilogue: 64 h x 14 n, 7 m each ----
    const int s_  = shift_p ? shift_p[0] : 1;
    const int s28 = ((s_ % 28) + 28) % 28;
    const int s14 = ((s_ % 14) + 14) % 14;

#pragma unroll
    for (int it = 0; it < 4; ++it) {
        int idx = it * THREADS + tid;   // 0..895
        int h_l = idx & 63;
        int nb  = idx >> 6;             // 0..13

        float2 w0p = __ldg(reinterpret_cast<const float2*>(w0) + (h0 + h_l));

        int n2[2];
        float wv[2];
#pragma unroll
        for (int e = 0; e < 2; ++e) {
            int g  = (nb * 2 + e - s28 + 56) % 28;
            int n1 = g >> 1;
            int e1 = g & 1;
            n2[e]  = (n1 - s14 + 14) % 14;
            wv[e]  = e1 ? w0p.y : w0p.x;
        }

        float* obase = out + ((size_t)(b * H_ + h0 + h_l) * C2_ + nb) * S_ + 7 * mh;
#pragma unroll
        for (int mm = 0; mm < 7; ++mm) {
            float v = sm[(mm * 14 + n2[0]) * CS_STRIDE + h_l] * wv[0]
                    + sm[(mm * 14 + n2[1]) * CS_STRIDE + h_l] * wv[1];
            obase[mm] = v;
        }
    }
}

// ---------------------------------------------------------------------------
extern "C" void kernel_launch(void* const* d_in, const int* in_sizes, int n_in,
                              void* d_out, int out_size)
{
    const float* x     = (const float*)d_in[0];
    const float* w0    = (const float*)d_in[1];
    const float* w1    = (const float*)d_in[2];
    const int*   shift = (n_in >= 4) ? (const int*)d_in[3] : nullptr;

    (void)in_sizes; (void)out_size;

    prep_kernel<<<1024 + WBLK, 448>>>(x, w1);

    cudaFuncSetAttribute(fused_kernel,
                         cudaFuncAttributeMaxDynamicSharedMemorySize,
                         SMEM_WORDS * 4);
    fused_kernel<<<B_ * 8, THREADS, SMEM_WORDS * 4>>>(w0, shift, (float*)d_out);
}

// round 16
// speedup vs baseline: 1.0373x; 1.0373x over previous
#include <cuda_runtime.h>
#include <cuda_fp16.h>
#include <cstdint>

// Problem constants
#define B_  128
#define C2_ 14
#define S_  14
#define H_  256

#define THREADS 224   // 7 warps

// A (x window) smem geometry, word units (1 word = 4B = 1 half2 slot):
//   addr = 336*plane + 24*n + slot ;  336 = 14*24 so 336*mr+24*nr = 24*r
//   row stride 24 (== 24 mod 32) -> LDS.64 banks 24q+2t conflict-free
#define ROW_S   24
#define PLANE_S 336
#define XBUF_W  (9 * PLANE_S)        // 3024 words per buffer (9 planes)
#define BS_W    (2 * XBUF_W)         // 6048
#define BS_BUF  (64 * ROW_S)         // 1536 words per B chunk (N=64)
#define NBUF_B  4
#define CS_STRIDE 68
#define SMEM_WORDS (BS_W + NBUF_B * BS_BUF)   // 12192 words = 48768 B

// Packed fp16 k-pair scratch (rebuilt each launch)
#define WPRE_N (12 * 4 * 64 * 16)               // 49152 half2
__device__ __half2 g_xpre[(size_t)B_ * 16 * 14 * 64];   // 7.3 MB
__device__ __half2 g_wpre[WPRE_N];                      // 196 KB

#define WBLK ((WPRE_N + 447) / 448)             // 110

// slot s -> pair p  (inverse of addr(p) = (p&8)|((p&3)<<1)|((p&4)>>2))
__device__ __forceinline__ int slot2pair(int s) {
    return (s & 8) | ((s >> 1) & 3) | ((s & 1) << 2);
}

__device__ __forceinline__ void mma_f16(float c[4],
                                        unsigned a0, unsigned a1, unsigned a2, unsigned a3,
                                        unsigned b0, unsigned b1) {
    asm volatile(
        "mma.sync.aligned.m16n8k16.row.col.f32.f16.f16.f32 "
        "{%0,%1,%2,%3}, {%4,%5,%6,%7}, {%8,%9}, {%0,%1,%2,%3};"
        : "+f"(c[0]), "+f"(c[1]), "+f"(c[2]), "+f"(c[3])
        : "r"(a0), "r"(a1), "r"(a2), "r"(a3), "r"(b0), "r"(b1));
}

__device__ __forceinline__ void cp16(unsigned dst, const void* src) {
    asm volatile("cp.async.cg.shared.global [%0], [%1], 16;"
                 :: "r"(dst), "l"(src) : "memory");
}
#define CP_COMMIT() asm volatile("cp.async.commit_group;" ::: "memory")
#define CP_WAIT2()  asm volatile("cp.async.wait_group 2;" ::: "memory")

// ---------------------------------------------------------------------------
// prep (merged): blocks [0,1024) build xpre; blocks [1024,1024+WBLK) build wpre.
// ---------------------------------------------------------------------------
__global__ __launch_bounds__(448) void prep_kernel(
    const float* __restrict__ x, const float* __restrict__ w1)
{
    const int bx  = blockIdx.x;
    const int tid = threadIdx.x;

    if (bx < 1024) {
        __shared__ float xs[6272];
        const int jb = bx & 3;
        const int b  = (bx >> 2) & 127;
        const int ph = bx >> 9;            // 0,1: which 8 planes

        const float4* src = reinterpret_cast<const float4*>(
            x + (size_t)b * 25088 + jb * 6272);
#pragma unroll
        for (int k = 0; k < 4; ++k) {
            int p = tid + k * 448;
            if (p < 1568) reinterpret_cast<float4*>(xs)[p] = __ldg(src + p);
        }
        __syncthreads();

        const int half = tid >= 224;
        const int sub  = tid - 224 * half;
        const int nn   = sub >> 4;
        const int s    = sub & 15;
        const int pp   = slot2pair(s);
        const float* r0 = xs + (2 * pp)     * 196 + nn * 14;
        const float* r1 = xs + (2 * pp + 1) * 196 + nn * 14;

        __half2* wb = g_xpre + ((size_t)b * 16 * 14 + nn) * 64 + jb * 16 + s;
#pragma unroll
        for (int k = 0; k < 4; ++k) {
            int mp = ph * 8 + half * 4 + k;
            __half2 v = (mp >= 1 && mp <= 14)
                      ? __floats2half2_rn(r0[mp - 1], r1[mp - 1])
                      : __floats2half2_rn(0.0f, 0.0f);
            wb[(size_t)mp * 14 * 64] = v;
        }
    } else {
        int idx = (bx - 1024) * 448 + tid;
        if (idx < WPRE_N) {
            int s  = idx & 15;
            int n  = (idx >> 4) & 63;
            int hq = (idx >> 10) & 3;
            int c  = idx >> 12;
            int jb = c / 3;
            int ii = c - 3 * jb;
            int pp = slot2pair(s);
            int j  = jb * 32 + 2 * pp;
            int h  = hq * 64 + n;
            float lo = __ldg(w1 + (size_t)(j * 3 + ii) * H_ + h);
            float hi = __ldg(w1 + (size_t)((j + 1) * 3 + ii) * H_ + h);
            g_wpre[idx] = __floats2half2_rn(lo, hi);
        }
    }
}

// ---------------------------------------------------------------------------
// Fused fp16 GEMM + roll epilogue. Block = (b, m-half, 64-h chunk).
// M=112 rows, N=64, K=384 in 12 chunks of 32. 4 CTAs/SM (28 warps):
// reg-lean staging (indices recomputed per issue), __launch_bounds__(224,4).
// ---------------------------------------------------------------------------
__global__ void __launch_bounds__(THREADS, 4) fused_kernel(
    const float* __restrict__ w0,      // (H, 2)
    const int*   __restrict__ shift_p, // scalar (may be null -> 1)
    float*       __restrict__ out)     // (B, H, C2, S)
{
    extern __shared__ float sm[];
    unsigned sbase;
    asm("{ .reg .u64 t; cvta.to.shared.u64 t, %1; cvt.u32.u64 %0, t; }"
        : "=r"(sbase) : "l"(sm));

    const int bid = blockIdx.x;
    const int b   = bid >> 3;
    const int mh  = (bid >> 2) & 1;
    const int hh  = bid & 3;
    const int h0  = hh * 64;

    const int tid  = threadIdx.x;
    const int w    = tid >> 5;
    const int lane = tid & 31;
    const int t    = lane & 3;
    const int q    = lane >> 2;

    const __half2* xpb = g_xpre + ((size_t)b * 16 + 7 * mh) * 14 * 64;

    // x staging: 126 rows x 4 segs = 504 cp16 (indices recomputed -> no regs)
    auto issue_x = [&](int jb) {
        unsigned dbase = sbase + (unsigned)((jb & 1) * XBUF_W) * 4u;
#pragma unroll
        for (int k = 0; k < 3; ++k) {
            int p = tid + k * THREADS;
            if (p < 504) {
                int row = p >> 2, seg = p & 3;
                int lp  = row / 14;
                int nn  = row - lp * 14;
                const __half2* src = xpb + (size_t)(lp * 14 + nn) * 64
                                   + jb * 16 + seg * 4;
                unsigned dst = dbase + (unsigned)(PLANE_S * lp + ROW_S * nn
                                                  + 4 * seg) * 4u;
                cp16(dst, src);
            }
        }
    };
    // B staging: 64 rows x 4 segs = 256 cp16
    auto issue_b = [&](int c2, int buf) {
        const __half2* bsrc = g_wpre + (size_t)(c2 * 4 + hh) * 1024;
        unsigned dbase = sbase + (unsigned)(BS_W + buf * BS_BUF) * 4u;
#pragma unroll
        for (int k = 0; k < 2; ++k) {
            int p = tid + k * THREADS;
            if (p < 256) {
                int row = p >> 2, seg = p & 3;
                cp16(dbase + (unsigned)(row * ROW_S + 4 * seg) * 4u,
                     bsrc + row * 16 + seg * 4);
            }
        }
    };

    // Per-thread A base offsets (words): rows q, q+8 of warp tile m16
    int pa[2];
#pragma unroll
    for (int u = 0; u < 2; ++u) {
        int r  = 16 * w + q + 8 * u;
        int mr = r / 14;
        int nr = r - mr * 14;
        if (mr > 6) mr = 6;            // pad rows -> harmless valid data
        pa[u] = PLANE_S * mr + ROW_S * nr + 2 * t;
    }

    // Prologue: x0 + B chunks 0,1,2
    issue_x(0);
    issue_b(0, 0);
    CP_COMMIT();
    issue_b(1, 1);
    CP_COMMIT();
    issue_b(2, 2);
    CP_COMMIT();

    float cf[8][4];
#pragma unroll
    for (int f = 0; f < 8; ++f)
#pragma unroll
        for (int r = 0; r < 4; ++r) cf[f][r] = 0.0f;

    const int pbq = ROW_S * q + 2 * t;

    // ---- Main loop: 12 chunks = 4 j-blocks x 3 i; 2 k16 MMA steps each ----
#pragma unroll 1
    for (int jb = 0; jb < 4; ++jb) {
        const int xw = (jb & 1) * XBUF_W;

#pragma unroll
        for (int ii = 0; ii < 3; ++ii) {
            CP_WAIT2();
            __syncthreads();

            const int c = 3 * jb + ii;
            if (ii == 0 && jb < 3) issue_x(jb + 1);
            if (c < 9) issue_b(c + 3, (c + 3) & 3);
            CP_COMMIT();

            const int bw = BS_W + (c & 3) * BS_BUF + pbq;
            const int aw = xw + PLANE_S * ii;

#pragma unroll
            for (int s = 0; s < 2; ++s) {
                const int ao = aw + 8 * s;
                float2 L1 = *reinterpret_cast<const float2*>(&sm[pa[0] + ao]);
                float2 L2 = *reinterpret_cast<const float2*>(&sm[pa[1] + ao]);
                unsigned a0 = __float_as_uint(L1.x), a2 = __float_as_uint(L1.y);
                unsigned a1 = __float_as_uint(L2.x), a3 = __float_as_uint(L2.y);
#pragma unroll
                for (int fn = 0; fn < 8; ++fn) {
                    float2 bp = *reinterpret_cast<const float2*>(
                        &sm[bw + fn * (8 * ROW_S) + 8 * s]);
                    mma_f16(cf[fn], a0, a1, a2, a3,
                            __float_as_uint(bp.x), __float_as_uint(bp.y));
                }
            }
        }
    }

    __syncthreads();   // C tile aliases x/B regions -> drain reads first

    // ---- Write C tile to smem rows [r][CS_STRIDE] (112 x 68 = 7616 w) ----
#pragma unroll
    for (int fn = 0; fn < 8; ++fn) {
        const float* cc = cf[fn];
        int r1  = 16 * w + q;
        int r2  = r1 + 8;
        int col = 8 * fn + 2 * t;
        *reinterpret_cast<float2*>(&sm[r1 * CS_STRIDE + col]) = make_float2(cc[0], cc[1]);
        *reinterpret_cast<float2*>(&sm[r2 * CS_STRIDE + col]) = make_float2(cc[2], cc[3]);
    }
    __syncthreads();

    // ---- Fused roll epilogue: 64 h x 14 n, 7 m each ----
    const int s_  = shift_p ? shift_p[0] : 1;
    const int s28 = ((s_ % 28) + 28) % 28;
    const int s14 = ((s_ % 14) + 14) % 14;

#pragma unroll
    for (int it = 0; it < 4; ++it) {
        int idx = it * THREADS + tid;   // 0..895
        int h_l = idx & 63;
        int nb  = idx >> 6;             // 0..13

        float2 w0p = __ldg(reinterpret_cast<const float2*>(w0) + (h0 + h_l));

        int n2[2];
        float wv[2];
#pragma unroll
        for (int e = 0; e < 2; ++e) {
            int g  = (nb * 2 + e - s28 + 56) % 28;
            int n1 = g >> 1;
            int e1 = g & 1;
            n2[e]  = (n1 - s14 + 14) % 14;
            wv[e]  = e1 ? w0p.y : w0p.x;
        }

        float* obase = out + ((size_t)(b * H_ + h0 + h_l) * C2_ + nb) * S_ + 7 * mh;
#pragma unroll
        for (int mm = 0; mm < 7; ++mm) {
            float v = sm[(mm * 14 + n2[0]) * CS_STRIDE + h_l] * wv[0]
                    + sm[(mm * 14 + n2[1]) * CS_STRIDE + h_l] * wv[1];
            obase[mm] = v;
        }
    }
}

// ---------------------------------------------------------------------------
extern "C" void kernel_launch(void* const* d_in, const int* in_sizes, int n_in,
                              void* d_out, int out_size)
{
    const float* x     = (const float*)d_in[0];
    const float* w0    = (const float*)d_in[1];
    const float* w1    = (const float*)d_in[2];
    const int*   shift = (n_in >= 4) ? (const int*)d_in[3] : nullptr;

    (void)in_sizes; (void)out_size;

    prep_kernel<<<1024 + WBLK, 448>>>(x, w1);

    cudaFuncSetAttribute(fused_kernel,
                         cudaFuncAttributeMaxDynamicSharedMemorySize,
                         SMEM_WORDS * 4);
    fused_kernel<<<B_ * 8, THREADS, SMEM_WORDS * 4>>>(w0, shift, (float*)d_out);
}